// round 14
// baseline (speedup 1.0000x reference)
#include <cuda_runtime.h>
#include <cuda_fp16.h>
#include <stdint.h>
#include <math.h>

// Problem constants
#define BATCH   16384
#define OBS     568
#define HDIM    256
#define SELFD   36
#define OTHD    28
#define NOTH    19
#define MROWS   (BATCH*NOTH)
#define XWP     284          // OBS/2 half2 words per x row

// ---------------------------------------------------------------------------
// Scratch (device globals; allocation is forbidden)
// ---------------------------------------------------------------------------
__device__ float   g_mu  [BATCH*HDIM];
__device__ float   g_q   [BATCH*HDIM];
__device__ float   g_sev [BATCH*HDIM];
__device__ float   g_spa [BATCH*HDIM];
__device__ __half2 g_zh  [BATCH*128];
__device__ __half2 g_selfh[BATCH*128];
__device__ __half2 g_hh  [BATCH*128];
__device__ __half2 g_kh  [MROWS*128];
__device__ __half2 g_vh  [MROWS*128];
__device__ __half2 g_xh  [BATCH*XWP];
// Blocked packed weights: per region, word offset of (tile, half, n, kp) =
//   base + ((tile*2 + half)*128 + n)*16 + kp, value = half2(W[2k][col], W[2k+1][col])
// with k = kpOff + tile*16 + kp, col = half*128 + n; zero-padded past kpLen.
#define WB_MU   0        // 18 tiles
#define WB_VAR  73728    // 18
#define WB_SELF 147456   // 2
#define WB_OTH  155648   // 1
#define WB_Q    159744   // 8
#define WB_K    192512   // 8
#define WB_VLO  225280   // 8
#define WB_VHI  258048   // 8
#define WB_ALO  290816   // 8
#define WB_AHI  323584   // 8
#define WB_END  356352
__device__ __half2 g_wp[WB_END];

// ---------------------------------------------------------------------------
// Helpers
// ---------------------------------------------------------------------------
__device__ __forceinline__ uint32_t smem_u32(const void* p) {
    uint32_t a;
    asm("{ .reg .u64 t; cvta.to.shared.u64 t, %1; cvt.u32.u64 %0, t; }"
        : "=r"(a) : "l"(p));
    return a;
}
__device__ __forceinline__ void cpa16(uint32_t dst, const void* src, int bytes) {
    asm volatile("cp.async.cg.shared.global [%0], [%1], 16, %2;"
                 :: "r"(dst), "l"(src), "r"(bytes) : "memory");
}
#define CP_COMMIT() asm volatile("cp.async.commit_group;" ::: "memory")
#define CP_WAIT2()  asm volatile("cp.async.wait_group 2;" ::: "memory")
#define MMA_F16(acc, a, b) \
    asm volatile( \
        "mma.sync.aligned.m16n8k16.row.col.f32.f16.f16.f32 " \
        "{%0,%1,%2,%3},{%4,%5,%6,%7},{%8,%9},{%0,%1,%2,%3};" \
        : "+f"((acc)[0]), "+f"((acc)[1]), "+f"((acc)[2]), "+f"((acc)[3]) \
        : "r"((a)[0]), "r"((a)[1]), "r"((a)[2]), "r"((a)[3]), \
          "r"((b)[0]), "r"((b)[1]))
#define LDSM_X4(r0, r1, r2, r3, addr) \
    asm volatile("ldmatrix.sync.aligned.m8n8.x4.shared.b16 {%0,%1,%2,%3}, [%4];" \
                 : "=r"(r0), "=r"(r1), "=r"(r2), "=r"(r3) : "r"(addr))

// A smem layout (interleaved for ldmatrix): row m, kp-chunk c (16B):
//   p = m>>1, hs = m&1, word = p*prow + ((hs*4 + c) ^ (p&7))*4 + win
// B smem layout (n-major for ldmatrix): row n (64B), chunk c = 2ks+half:
//   byte = n*64 + ((c ^ ((n>>1)&3)) << 4)   -- conflict-free LDSM + STS

// ---------------------------------------------------------------------------
// FP16 mma.sync GEMM, cp.async 4-stage pipeline, ldmatrix A+B fragments.
// C[M,256] = epi(A[M,2*Kp] @ W); W = blocked region (see above).
// BM=64, BN=128, BKp=16, 256 threads (8 warps 2x4), warp tile 32x32.
// 3 CTAs/SM (occupancy-optimized; stage = 4KB A + 8KB B, 4 stages = 48KB).
// EPI : 0 = +bias; 1 = relu(+bias); 2 = relu(+extra[row*256+col]);
//       3 = z-fusion: lv=acc+bias; C = fma(aux, exp(0.5*lv), extra) per elem
// OUTH: 1 = write half2-packed Ch[row*128+col/2]; 0 = write fp32 Cf.
// ---------------------------------------------------------------------------
#define STAGE_BYTES 12288
#define GSMEM_BYTES (4*STAGE_BYTES)

template<int EPI, int OUTH>
__global__ void __launch_bounds__(256, 3)
hgemm(const __half2* __restrict__ A, int lda,
      const __half2* __restrict__ W,
      const float* __restrict__ bias,
      const float* __restrict__ extra,
      const float* __restrict__ aux,
      float* __restrict__ Cf, __half2* __restrict__ Ch,
      int Kp)
{
    extern __shared__ char sm[];
    const uint32_t sb = smem_u32(sm);
    const int tid  = threadIdx.x;
    const int lane = tid & 31;
    const int wid  = tid >> 5;
    const int wm   = wid >> 2;          // 0..1
    const int wn   = wid & 3;           // 0..3
    const int g    = lane >> 2;
    const int t    = lane & 3;

    const long rowBase = (long)blockIdx.y * 64;
    const int  nHalf   = blockIdx.x;
    const int  colBase = nHalf * 128;

    // A producer: 1 chunk of 16B per thread (64 rows x 4 chunks)
    const int am = tid >> 2;            // 0..63
    const int ac = tid & 3;             // 0..3
    const long abase = (rowBase + am) * (long)lda;
    const uint32_t adst = (uint32_t)(((am >> 1) * 32
                        + (((am & 1) * 4 + ac) ^ ((am >> 1) & 7)) * 4) * 4);
    // B producer: 2 chunks per thread
    int bn[2], bc[2]; uint32_t bdst[2];
#pragma unroll
    for (int j = 0; j < 2; j++) {
        int idx = tid + j * 256;
        bn[j] = idx >> 2;               // 0..127
        bc[j] = idx & 3;
        bdst[j] = (uint32_t)(bn[j] * 64 + ((bc[j] ^ ((bn[j] >> 1) & 3)) << 4));
    }

    auto issue = [&](int tt, int s) {
        const int ktp = tt << 4;
        const uint32_t sA = sb + (uint32_t)s * STAGE_BYTES;
        const uint32_t sB = sA + 4096u;
        {
            int kg  = ktp + ac * 4;
            int rem = Kp - kg;
            int bytes = (rem <= 0) ? 0 : ((rem >= 4) ? 16 : rem * 4);
            cpa16(sA + adst, A + abase + (bytes ? kg : 0), bytes);
        }
#pragma unroll
        for (int j = 0; j < 2; j++) {
            const __half2* src = W + ((long)(tt * 2 + nHalf) * 128 + bn[j]) * 16 + bc[j] * 4;
            cpa16(sB + bdst[j], src, 16);
        }
    };

    // ldmatrix lane geometry: A fragments
    const int lm = ((lane >> 3) & 1) * 8 + (lane & 7);
    const int lc = lane >> 4;
    int apb[2], ahs4[2], ap7[2];
#pragma unroll
    for (int mi = 0; mi < 2; mi++) {
        int m = wm * 32 + mi * 16 + lm;
        apb[mi]  = (m >> 1) * 32;
        ahs4[mi] = (m & 1) * 4;
        ap7[mi]  = (m >> 1) & 7;
    }
    // ldmatrix lane geometry: B fragments
    const int bl_m = lane >> 3;
    const int bl_r = lane & 7;
    const int b_half = bl_m & 1;
    int nb64[2], nbx[2];
#pragma unroll
    for (int ci = 0; ci < 2; ci++) {
        int ni = 2 * ci + (bl_m >> 1);
        int n  = wn * 32 + ni * 8 + bl_r;
        nb64[ci] = n * 64;
        nbx[ci]  = (n >> 1) & 3;
    }

    float acc[2][4][4];
#pragma unroll
    for (int mi = 0; mi < 2; mi++)
#pragma unroll
        for (int ni = 0; ni < 4; ni++)
#pragma unroll
            for (int c = 0; c < 4; c++) acc[mi][ni][c] = 0.f;

    const int nt = (Kp + 15) >> 4;
#pragma unroll
    for (int s = 0; s < 3; s++) {
        if (s < nt) issue(s, s);
        CP_COMMIT();
    }

    for (int tt = 0; tt < nt; tt++) {
        CP_WAIT2();
        __syncthreads();
        const int tn = tt + 3;
        if (tn < nt) issue(tn, tn & 3);
        CP_COMMIT();

        const uint32_t sA = sb + (uint32_t)(tt & 3) * STAGE_BYTES;
        const uint32_t sB = sA + 4096u;
#pragma unroll
        for (int ks = 0; ks < 2; ks++) {
            unsigned a[2][4], b[4][2];
            const int c = 2 * ks + lc;
#pragma unroll
            for (int mi = 0; mi < 2; mi++) {
                uint32_t addr = sA + (uint32_t)((apb[mi] + ((ahs4[mi] + c) ^ ap7[mi]) * 4) * 4);
                LDSM_X4(a[mi][0], a[mi][1], a[mi][2], a[mi][3], addr);
            }
#pragma unroll
            for (int ci = 0; ci < 2; ci++) {
                uint32_t addr = sB + (uint32_t)(nb64[ci] + (((2 * ks + b_half) ^ nbx[ci]) << 4));
                LDSM_X4(b[2 * ci][0], b[2 * ci][1], b[2 * ci + 1][0], b[2 * ci + 1][1], addr);
            }
#pragma unroll
            for (int mi = 0; mi < 2; mi++)
#pragma unroll
                for (int ni = 0; ni < 4; ni++)
                    MMA_F16(acc[mi][ni], a[mi], b[ni]);
        }
    }

#pragma unroll
    for (int mi = 0; mi < 2; mi++) {
#pragma unroll
        for (int d = 0; d < 2; d++) {
            const long row = rowBase + wm * 32 + mi * 16 + g + d * 8;
#pragma unroll
            for (int ni = 0; ni < 4; ni++) {
                const int col = colBase + wn * 32 + ni * 8 + 2 * t;
                float v0 = acc[mi][ni][2 * d];
                float v1 = acc[mi][ni][2 * d + 1];
                if (EPI == 3) {
                    v0 += bias[col]; v1 += bias[col + 1];
                    const float* murow  = extra + row * 256;
                    const float* epsrow = aux + row * 256;
                    v0 = fmaf(epsrow[col],     expf(0.5f * v0), murow[col]);
                    v1 = fmaf(epsrow[col + 1], expf(0.5f * v1), murow[col + 1]);
                } else if (EPI == 2) {
                    v0 += extra[row * 256 + col]; v1 += extra[row * 256 + col + 1];
                    v0 = fmaxf(v0, 0.f); v1 = fmaxf(v1, 0.f);
                } else {
                    v0 += bias[col]; v1 += bias[col + 1];
                    if (EPI == 1) { v0 = fmaxf(v0, 0.f); v1 = fmaxf(v1, 0.f); }
                }
                if (OUTH)
                    Ch[row * 128 + (col >> 1)] = __floats2half2_rn(v0, v1);
                else
                    *reinterpret_cast<float2*>(&Cf[row * 256 + col]) = make_float2(v0, v1);
            }
        }
    }
}

// ---------------------------------------------------------------------------
// Fused oth -> (k, v), fp16 + ldmatrix A&B. Per CTA: 128 agent rows, 512 thr.
// smem words: OTH 16384 (interleaved, prow=256), A1 2048 (prow=32),
//             4 B stages x 2048 (n-major blocked layout).
// ---------------------------------------------------------------------------
#define F_OTH 0
#define F_A1  16384
#define F_STG 18432
#define FSMEM_BYTES 106496

__global__ void __launch_bounds__(512, 2)
fused_okv(const __half2* __restrict__ xh,
          const __half2* __restrict__ WBoth, const float* __restrict__ both,
          const __half2* __restrict__ WBk,   const float* __restrict__ bk_,
          const __half2* __restrict__ WBvlo,
          const float* __restrict__ sev,
          __half2* __restrict__ kb, __half2* __restrict__ vb)
{
    extern __shared__ char sm[];
    unsigned* smw = (unsigned*)sm;
    const uint32_t sb = smem_u32(sm);
    const int tid  = threadIdx.x;
    const int lane = tid & 31;
    const int wid  = tid >> 5;
    const int wm   = wid >> 2;   // 0..3
    const int wn   = wid & 3;    // 0..3
    const int g    = lane >> 2;
    const int t    = lane & 3;
    const long rowBase = (long)blockIdx.x * 128;

    const int lm = ((lane >> 3) & 1) * 8 + (lane & 7);
    const int lc = lane >> 4;
    int apbO[2], apbA[2], ahs4[2], ap7[2];
#pragma unroll
    for (int mi = 0; mi < 2; mi++) {
        int m = wm * 32 + mi * 16 + lm;
        apbO[mi] = (m >> 1) * 256;   // OTH prow = 256 words
        apbA[mi] = (m >> 1) * 32;    // A1 prow = 32 words
        ahs4[mi] = (m & 1) * 4;
        ap7[mi]  = (m >> 1) & 7;
    }
    // B ldmatrix geometry
    const int bl_m = lane >> 3;
    const int bl_r = lane & 7;
    const int b_half = bl_m & 1;
    int nb64[2], nbx[2];
#pragma unroll
    for (int ci = 0; ci < 2; ci++) {
        int ni = 2 * ci + (bl_m >> 1);
        int n  = wn * 32 + ni * 8 + bl_r;
        nb64[ci] = n * 64;
        nbx[ci]  = (n >> 1) & 3;
    }
    // B producer geometry (512 threads = 128n x 4c)
    const int pn = tid >> 2, pc = tid & 3;
    const uint32_t pdst = (uint32_t)(pn * 64 + ((pc ^ ((pn >> 1) & 3)) << 4));

    // ---- A1: agents tile (plain word loads into interleaved layout) ----
    for (int it = tid; it < 2048; it += 512) {
        const int m = it >> 4, w = it & 15;
        unsigned val = 0;
        if (w < 14) {
            long row = rowBase + m;
            int bb = (int)(row / NOTH);
            int nn = (int)(row - (long)bb * NOTH);
            val = *reinterpret_cast<const unsigned*>(&xh[(long)bb * XWP + 18 + nn * 14 + w]);
        }
        const int p = m >> 1, hs = m & 1, c = w >> 2, win = w & 3;
        smw[F_A1 + p * 32 + ((hs * 4 + c) ^ (p & 7)) * 4 + win] = val;
    }
    // ---- W_oth B tiles (2 col-halves, blocked+padded) into stages 0,1 ----
#pragma unroll
    for (int h = 0; h < 2; h++) {
        const __half2* src = WBoth + ((long)h * 128 + pn) * 16 + pc * 4;
        cpa16(sb + (uint32_t)(F_STG + h * 2048) * 4 + pdst, src, 16);
    }
    CP_COMMIT();
    asm volatile("cp.async.wait_group 0;" ::: "memory");
    __syncthreads();

    // ---- stage 1: oth = relu(agents @ W_oth + b) -> OTH (half2, interleaved) ----
    for (int h = 0; h < 2; h++) {
        float acc[2][4][4];
#pragma unroll
        for (int mi = 0; mi < 2; mi++)
#pragma unroll
            for (int ni = 0; ni < 4; ni++)
#pragma unroll
                for (int c = 0; c < 4; c++) acc[mi][ni][c] = 0.f;
        const uint32_t sB = sb + (uint32_t)(F_STG + h * 2048) * 4;
#pragma unroll
        for (int ks = 0; ks < 2; ks++) {
            unsigned a[2][4], b[4][2];
            const int c = 2 * ks + lc;
#pragma unroll
            for (int mi = 0; mi < 2; mi++) {
                uint32_t addr = sb + (uint32_t)((F_A1 + apbA[mi] + ((ahs4[mi] + c) ^ ap7[mi]) * 4) * 4);
                LDSM_X4(a[mi][0], a[mi][1], a[mi][2], a[mi][3], addr);
            }
#pragma unroll
            for (int ci = 0; ci < 2; ci++) {
                uint32_t addr = sB + (uint32_t)(nb64[ci] + (((2 * ks + b_half) ^ nbx[ci]) << 4));
                LDSM_X4(b[2 * ci][0], b[2 * ci][1], b[2 * ci + 1][0], b[2 * ci + 1][1], addr);
            }
#pragma unroll
            for (int mi = 0; mi < 2; mi++)
#pragma unroll
                for (int ni = 0; ni < 4; ni++)
                    MMA_F16(acc[mi][ni], a[mi], b[ni]);
        }
        // epilogue -> OTH (interleaved: chunk c = h*4 + wn lines, win = t)
#pragma unroll
        for (int mi = 0; mi < 2; mi++)
#pragma unroll
            for (int d = 0; d < 2; d++) {
                const int rm = wm * 32 + mi * 16 + g + d * 8;
                const int p = rm >> 1, hs = rm & 1;
#pragma unroll
                for (int ni = 0; ni < 4; ni++) {
                    const int col = h * 128 + wn * 32 + ni * 8 + 2 * t;
                    float v0 = fmaxf(acc[mi][ni][2 * d]     + both[col],     0.f);
                    float v1 = fmaxf(acc[mi][ni][2 * d + 1] + both[col + 1], 0.f);
                    __half2 hv = __floats2half2_rn(v0, v1);
                    const int line = h * 4 + wn;             // c>>2
                    smw[F_OTH + p * 256 + line * 32 + ((hs * 4 + ni) ^ (p & 7)) * 4 + t] =
                        *reinterpret_cast<unsigned*>(&hv);
                }
            }
    }
    __syncthreads();

    // ---- stage 2: 4 chunks {k-lo, k-hi, v-lo, v-hi}, Kp=128, 8 tiles, 4-stage ----
    for (int cc = 0; cc < 4; cc++) {
        const __half2* W = (cc < 2) ? WBk : WBvlo;
        const int nh = cc & 1;
        __half2* Co = (cc < 2) ? kb : vb;
        const int colOff = nh * 128;

        auto issueB = [&](int tt, int s) {
            const __half2* src = W + ((long)(tt * 2 + nh) * 128 + pn) * 16 + pc * 4;
            cpa16(sb + (uint32_t)(F_STG + s * 2048) * 4 + pdst, src, 16);
        };

        float acc[2][4][4];
#pragma unroll
        for (int mi = 0; mi < 2; mi++)
#pragma unroll
            for (int ni = 0; ni < 4; ni++)
#pragma unroll
                for (int c = 0; c < 4; c++) acc[mi][ni][c] = 0.f;

#pragma unroll
        for (int s = 0; s < 3; s++) {
            issueB(s, s);
            CP_COMMIT();
        }

        for (int tt = 0; tt < 8; tt++) {
            CP_WAIT2();
            __syncthreads();
            if (tt + 3 < 8) issueB(tt + 3, (tt + 3) & 3);
            CP_COMMIT();

            const uint32_t sB = sb + (uint32_t)(F_STG + (tt & 3) * 2048) * 4;
#pragma unroll
            for (int ks = 0; ks < 2; ks++) {
                unsigned a[2][4], b[4][2];
                const int c3 = 2 * ks + lc;
#pragma unroll
                for (int mi = 0; mi < 2; mi++) {
                    uint32_t addr = sb + (uint32_t)((F_OTH + apbO[mi] + tt * 32
                                     + ((ahs4[mi] + c3) ^ ap7[mi]) * 4) * 4);
                    LDSM_X4(a[mi][0], a[mi][1], a[mi][2], a[mi][3], addr);
                }
#pragma unroll
                for (int ci = 0; ci < 2; ci++) {
                    uint32_t addr = sB + (uint32_t)(nb64[ci] + (((2 * ks + b_half) ^ nbx[ci]) << 4));
                    LDSM_X4(b[2 * ci][0], b[2 * ci][1], b[2 * ci + 1][0], b[2 * ci + 1][1], addr);
                }
#pragma unroll
                for (int mi = 0; mi < 2; mi++)
#pragma unroll
                    for (int ni = 0; ni < 4; ni++)
                        MMA_F16(acc[mi][ni], a[mi], b[ni]);
            }
        }

#pragma unroll
        for (int mi = 0; mi < 2; mi++)
#pragma unroll
            for (int d = 0; d < 2; d++) {
                const long row = rowBase + wm * 32 + mi * 16 + g + d * 8;
                const float* sv = (cc >= 2) ? (sev + (row / NOTH) * 256) : nullptr;
#pragma unroll
                for (int ni = 0; ni < 4; ni++) {
                    const int col = colOff + wn * 32 + ni * 8 + 2 * t;
                    float v0 = acc[mi][ni][2 * d];
                    float v1 = acc[mi][ni][2 * d + 1];
                    if (cc < 2) { v0 += bk_[col]; v1 += bk_[col + 1]; }
                    else        { v0 += sv[col];  v1 += sv[col + 1]; }
                    v0 = fmaxf(v0, 0.f); v1 = fmaxf(v1, 0.f);
                    Co[row * 128 + (col >> 1)] = __floats2half2_rn(v0, v1);
                }
            }
    }
}

// ---------------------------------------------------------------------------
// Packing kernels
// ---------------------------------------------------------------------------
__global__ void packWB(const float* __restrict__ Wmu, const float* __restrict__ Wvar,
                       const float* __restrict__ Wself, const float* __restrict__ Woth,
                       const float* __restrict__ Wq, const float* __restrict__ Wk,
                       const float* __restrict__ Wv, const float* __restrict__ Wa,
                       __half2* __restrict__ out)
{
    int i = blockIdx.x * blockDim.x + threadIdx.x;
    if (i >= WB_END) return;
    const float* src; int base, kpOff, kpLen;
    if      (i < WB_VAR)  { src = Wmu;   base = WB_MU;   kpOff = 0;   kpLen = 284; }
    else if (i < WB_SELF) { src = Wvar;  base = WB_VAR;  kpOff = 0;   kpLen = 284; }
    else if (i < WB_OTH)  { src = Wself; base = WB_SELF; kpOff = 0;   kpLen = 18;  }
    else if (i < WB_Q)    { src = Woth;  base = WB_OTH;  kpOff = 0;   kpLen = 14;  }
    else if (i < WB_K)    { src = Wq;    base = WB_Q;    kpOff = 0;   kpLen = 128; }
    else if (i < WB_VLO)  { src = Wk;    base = WB_K;    kpOff = 0;   kpLen = 128; }
    else if (i < WB_VHI)  { src = Wv;    base = WB_VLO;  kpOff = 0;   kpLen = 128; }
    else if (i < WB_ALO)  { src = Wv;    base = WB_VHI;  kpOff = 128; kpLen = 128; }
    else if (i < WB_AHI)  { src = Wa;    base = WB_ALO;  kpOff = 0;   kpLen = 128; }
    else                  { src = Wa;    base = WB_AHI;  kpOff = 128; kpLen = 128; }
    int r    = i - base;
    int tile = r >> 12;
    int rem  = r & 4095;
    int half = rem >> 11;
    int n    = (rem >> 4) & 127;
    int kp   = rem & 15;
    int kpl  = tile * 16 + kp;
    __half2 v = __floats2half2_rn(0.f, 0.f);
    if (kpl < kpLen) {
        int k   = kpOff + kpl;
        int col = half * 128 + n;
        v = __floats2half2_rn(src[(2 * k) * 256 + col], src[(2 * k + 1) * 256 + col]);
    }
    out[i] = v;
}
__global__ void packX(const float2* __restrict__ in, __half2* __restrict__ out, int n)
{
    int i = blockIdx.x * blockDim.x + threadIdx.x;
    if (i < n) {
        float2 f = in[i];
        out[i] = __floats2half2_rn(f.x, f.y);
    }
}

// ---------------------------------------------------------------------------
// Attention: scores = q.k/16 -> softmax(19) -> h = att @ v (half2 I/O)
// ---------------------------------------------------------------------------
__global__ void __launch_bounds__(256)
att_kernel(const float* __restrict__ q,
           const __half2* __restrict__ k2,
           const __half2* __restrict__ v2,
           __half2* __restrict__ h2,
           float* __restrict__ att_out)
{
    const int b   = blockIdx.x;
    const int tid = threadIdx.x;
    const int wid = tid >> 5;
    const int lane = tid & 31;

    __shared__ float qs[HDIM];
    __shared__ float sc[32];

    qs[tid] = q[(long)b * HDIM + tid];
    __syncthreads();

    for (int n = wid; n < NOTH; n += 8) {
        const __half2* kp = k2 + ((long)b * NOTH + n) * 128;
        float p = 0.f;
#pragma unroll
        for (int j = 0; j < 4; j++) {
            const int w = lane + 32 * j;
            float2 f = __half22float2(kp[w]);
            p = fmaf(qs[2 * w], f.x, p);
            p = fmaf(qs[2 * w + 1], f.y, p);
        }
#pragma unroll
        for (int off = 16; off > 0; off >>= 1)
            p += __shfl_xor_sync(0xffffffffu, p, off);
        if (lane == 0) sc[n] = p * 0.0625f;
    }
    __syncthreads();

    if (wid == 0) {
        float s = (lane < NOTH) ? sc[lane] : -INFINITY;
        float m = s;
#pragma unroll
        for (int off = 16; off > 0; off >>= 1)
            m = fmaxf(m, __shfl_xor_sync(0xffffffffu, m, off));
        float e = (lane < NOTH) ? expf(s - m) : 0.f;
        float sum = e;
#pragma unroll
        for (int off = 16; off > 0; off >>= 1)
            sum += __shfl_xor_sync(0xffffffffu, sum, off);
        const float a = e / sum;
        if (lane < NOTH) {
            sc[lane] = a;
            att_out[(long)b * NOTH + lane] = a;
        }
    }
    __syncthreads();

    if (tid < 128) {
        const __half2* vp = v2 + (long)b * NOTH * 128 + tid;
        float ax = 0.f, ay = 0.f;
#pragma unroll
        for (int n = 0; n < NOTH; n++) {
            float2 f = __half22float2(vp[(long)n * 128]);
            ax = fmaf(sc[n], f.x, ax);
            ay = fmaf(sc[n], f.y, ay);
        }
        h2[(long)b * 128 + tid] = __floats2half2_rn(ax, ay);
    }
}

// ---------------------------------------------------------------------------
// Launch
// ---------------------------------------------------------------------------
extern "C" void kernel_launch(void* const* d_in, const int* in_sizes, int n_in,
                              void* d_out, int out_size)
{
    const float* x      = (const float*)d_in[0];
    const float* eps    = (const float*)d_in[1];
    const float* W_mu   = (const float*)d_in[2];
    const float* b_mu   = (const float*)d_in[3];
    const float* W_var  = (const float*)d_in[4];
    const float* b_var  = (const float*)d_in[5];
    const float* W_self = (const float*)d_in[6];
    const float* b_self = (const float*)d_in[7];
    const float* W_oth  = (const float*)d_in[8];
    const float* b_oth  = (const float*)d_in[9];
    const float* W_q    = (const float*)d_in[10];
    const float* b_q    = (const float*)d_in[11];
    const float* W_k    = (const float*)d_in[12];
    const float* b_k    = (const float*)d_in[13];
    const float* W_v    = (const float*)d_in[14];
    const float* b_v    = (const float*)d_in[15];
    const float* W_a    = (const float*)d_in[16];
    const float* b_a    = (const float*)d_in[17];

    float* out_main = (float*)d_out;
    float* out_att  = (float*)d_out + (long)BATCH * HDIM;

    float *mu, *q, *sev, *spa;
    __half2 *zh, *selfh, *hh, *kh, *vh, *xh, *wp;
    cudaGetSymbolAddress((void**)&mu,    g_mu);
    cudaGetSymbolAddress((void**)&q,     g_q);
    cudaGetSymbolAddress((void**)&sev,   g_sev);
    cudaGetSymbolAddress((void**)&spa,   g_spa);
    cudaGetSymbolAddress((void**)&zh,    g_zh);
    cudaGetSymbolAddress((void**)&selfh, g_selfh);
    cudaGetSymbolAddress((void**)&hh,    g_hh);
    cudaGetSymbolAddress((void**)&kh,    g_kh);
    cudaGetSymbolAddress((void**)&vh,    g_vh);
    cudaGetSymbolAddress((void**)&xh,    g_xh);
    cudaGetSymbolAddress((void**)&wp,    g_wp);

    cudaFuncSetAttribute(hgemm<0,0>, cudaFuncAttributeMaxDynamicSharedMemorySize, GSMEM_BYTES);
    cudaFuncSetAttribute(hgemm<1,0>, cudaFuncAttributeMaxDynamicSharedMemorySize, GSMEM_BYTES);
    cudaFuncSetAttribute(hgemm<1,1>, cudaFuncAttributeMaxDynamicSharedMemorySize, GSMEM_BYTES);
    cudaFuncSetAttribute(hgemm<2,0>, cudaFuncAttributeMaxDynamicSharedMemorySize, GSMEM_BYTES);
    cudaFuncSetAttribute(hgemm<3,1>, cudaFuncAttributeMaxDynamicSharedMemorySize, GSMEM_BYTES);
    cudaFuncSetAttribute(fused_okv,  cudaFuncAttributeMaxDynamicSharedMemorySize, FSMEM_BYTES);

    // Pack operands (blocked weights + half2 x)
    packWB<<<(WB_END + 255) / 256, 256>>>(W_mu, W_var, W_self, W_oth,
                                          W_q, W_k, W_v, W_a, wp);
    {
        int nx = BATCH * XWP;
        packX<<<(nx + 255) / 256, 256>>>((const float2*)x, xh, nx);
    }

    const dim3 blk(256);
    const dim3 gB(2, BATCH / 64);   // BM=64 tiles

    // mu = x @ W_mu + b_mu (fp32 out)
    hgemm<0,0><<<gB, blk, GSMEM_BYTES>>>(xh, XWP, wp + WB_MU, b_mu, nullptr, nullptr, mu, nullptr, 284);
    // z = eps * exp(0.5*(x@W_var+b_var)) + mu  (half out)
    hgemm<3,1><<<gB, blk, GSMEM_BYTES>>>(xh, XWP, wp + WB_VAR, b_var, mu, eps, nullptr, zh, 284);
    // self_em = relu(x[:, :36] @ W_self + b) (half out)
    hgemm<1,1><<<gB, blk, GSMEM_BYTES>>>(xh, XWP, wp + WB_SELF, b_self, nullptr, nullptr, nullptr, selfh, 18);
    // sev = self_em @ W_v[256:] + b_v (fp32 out)
    hgemm<0,0><<<gB, blk, GSMEM_BYTES>>>(selfh, 128, wp + WB_VHI, b_v, nullptr, nullptr, sev, nullptr, 128);
    // fused: oth (smem) -> k, v (half out)
    fused_okv<<<MROWS / 128, 512, FSMEM_BYTES>>>(xh, wp + WB_OTH, b_oth,
                                                 wp + WB_K, b_k, wp + WB_VLO,
                                                 sev, kh, vh);
    // q = relu(z @ W_q + b) (fp32 out; feeds att only)
    hgemm<1,0><<<gB, blk, GSMEM_BYTES>>>(zh, 128, wp + WB_Q, b_q, nullptr, nullptr, q, nullptr, 128);
    // attention
    att_kernel<<<BATCH, 256>>>(q, kh, vh, hh, out_att);
    // spa = self_em @ W_a[256:] + b_a (fp32 out)
    hgemm<0,0><<<gB, blk, GSMEM_BYTES>>>(selfh, 128, wp + WB_AHI, b_a, nullptr, nullptr, spa, nullptr, 128);
    // out = relu(h @ W_a[:256] + spa) (fp32 out)
    hgemm<2,0><<<gB, blk, GSMEM_BYTES>>>(hh, 128, wp + WB_ALO, nullptr, spa, nullptr, out_main, nullptr, 128);
}

// round 16
// speedup vs baseline: 1.0381x; 1.0381x over previous
#include <cuda_runtime.h>
#include <cuda_fp16.h>
#include <stdint.h>
#include <math.h>

// Problem constants
#define BATCH   16384
#define OBS     568
#define HDIM    256
#define SELFD   36
#define OTHD    28
#define NOTH    19
#define MROWS   (BATCH*NOTH)
#define XWP     284          // OBS/2 half2 words per x row

// ---------------------------------------------------------------------------
// Scratch (device globals; allocation is forbidden)
// ---------------------------------------------------------------------------
__device__ float   g_q   [BATCH*HDIM];
__device__ float   g_sev [BATCH*HDIM];
__device__ float   g_spa [BATCH*HDIM];
__device__ __half2 g_zh  [BATCH*128];
__device__ __half2 g_selfh[BATCH*128];
__device__ __half2 g_hh  [BATCH*128];
__device__ __half2 g_kh  [MROWS*128];
__device__ __half2 g_vh  [MROWS*128];
__device__ __half2 g_xh  [BATCH*XWP];
// Blocked packed weights: per region, word offset of (tile, half, n, kp) =
//   base + ((tile*2 + half)*128 + n)*16 + kp, value = half2(W[2k][col], W[2k+1][col])
// with k = kpOff + tile*16 + kp, col = half*128 + n; zero-padded past kpLen.
#define WB_MU   0        // 18 tiles
#define WB_VAR  73728    // 18
#define WB_SELF 147456   // 2
#define WB_OTH  155648   // 1
#define WB_Q    159744   // 8
#define WB_K    192512   // 8
#define WB_VLO  225280   // 8
#define WB_VHI  258048   // 8
#define WB_ALO  290816   // 8
#define WB_AHI  323584   // 8
#define WB_END  356352
__device__ __half2 g_wp[WB_END];

// ---------------------------------------------------------------------------
// Helpers
// ---------------------------------------------------------------------------
__device__ __forceinline__ uint32_t smem_u32(const void* p) {
    uint32_t a;
    asm("{ .reg .u64 t; cvta.to.shared.u64 t, %1; cvt.u32.u64 %0, t; }"
        : "=r"(a) : "l"(p));
    return a;
}
__device__ __forceinline__ void cpa16(uint32_t dst, const void* src, int bytes) {
    asm volatile("cp.async.cg.shared.global [%0], [%1], 16, %2;"
                 :: "r"(dst), "l"(src), "r"(bytes) : "memory");
}
#define CP_COMMIT() asm volatile("cp.async.commit_group;" ::: "memory")
#define CP_WAIT2()  asm volatile("cp.async.wait_group 2;" ::: "memory")
#define MMA_F16(acc, a, b) \
    asm volatile( \
        "mma.sync.aligned.m16n8k16.row.col.f32.f16.f16.f32 " \
        "{%0,%1,%2,%3},{%4,%5,%6,%7},{%8,%9},{%0,%1,%2,%3};" \
        : "+f"((acc)[0]), "+f"((acc)[1]), "+f"((acc)[2]), "+f"((acc)[3]) \
        : "r"((a)[0]), "r"((a)[1]), "r"((a)[2]), "r"((a)[3]), \
          "r"((b)[0]), "r"((b)[1]))
#define LDSM_X4(r0, r1, r2, r3, addr) \
    asm volatile("ldmatrix.sync.aligned.m8n8.x4.shared.b16 {%0,%1,%2,%3}, [%4];" \
                 : "=r"(r0), "=r"(r1), "=r"(r2), "=r"(r3) : "r"(addr))

// A smem layout (interleaved for ldmatrix): row m, kp-chunk c (16B):
//   p = m>>1, hs = m&1, word = p*prow + ((hs*4 + c) ^ (p&7))*4 + win
// B smem layout (n-major for ldmatrix): row n (64B), chunk c = 2ks+half:
//   byte = n*64 + ((c ^ ((n>>1)&3)) << 4)   -- conflict-free LDSM + STS

// ---------------------------------------------------------------------------
// Single-B FP16 GEMM (R13 geometry): BM=128, BN=128, BKp=16, 256 thr (2x4),
// warp tile 64x32, 4-stage cp.async, ldmatrix A+B. 2 CTAs/SM.
// EPI : 1 = relu(+bias); 2 = relu(+extra[row*256+col]);
// OUTH: 1 = half2 out; 0 = fp32 out.
// ---------------------------------------------------------------------------
#define GS1_BYTES 65536   // 4 stages x (A 8KB + B 8KB)

template<int EPI, int OUTH>
__global__ void __launch_bounds__(256, 2)
hgemm(const __half2* __restrict__ A, int lda,
      const __half2* __restrict__ W,
      const float* __restrict__ bias,
      const float* __restrict__ extra,
      float* __restrict__ Cf, __half2* __restrict__ Ch,
      int Kp)
{
    extern __shared__ char sm[];
    const uint32_t sb = smem_u32(sm);
    const int tid  = threadIdx.x;
    const int lane = tid & 31;
    const int wid  = tid >> 5;
    const int wm   = wid >> 2;
    const int wn   = wid & 3;
    const int g    = lane >> 2;
    const int t    = lane & 3;

    const long rowBase = (long)blockIdx.y * 128;
    const int  nHalf   = blockIdx.x;
    const int  colBase = nHalf * 128;

    int am[2], ac[2]; long abase[2]; uint32_t adst[2];
#pragma unroll
    for (int j = 0; j < 2; j++) {
        int idx = tid + j * 256;
        am[j] = idx >> 2;
        ac[j] = idx & 3;
        abase[j] = (rowBase + am[j]) * (long)lda;
        int p = am[j] >> 1, hs = am[j] & 1;
        adst[j] = (uint32_t)((p * 32 + (((hs * 4) + ac[j]) ^ (p & 7)) * 4) * 4);
    }
    int bn[2], bc[2]; uint32_t bdst[2];
#pragma unroll
    for (int j = 0; j < 2; j++) {
        int idx = tid + j * 256;
        bn[j] = idx >> 2;
        bc[j] = idx & 3;
        bdst[j] = (uint32_t)(bn[j] * 64 + ((bc[j] ^ ((bn[j] >> 1) & 3)) << 4));
    }

    auto issue = [&](int tt, int s) {
        const int ktp = tt << 4;
        const uint32_t sA = sb + (uint32_t)s * 16384u;
        const uint32_t sB = sA + 8192u;
#pragma unroll
        for (int j = 0; j < 2; j++) {
            int kg  = ktp + ac[j] * 4;
            int rem = Kp - kg;
            int bytes = (rem <= 0) ? 0 : ((rem >= 4) ? 16 : rem * 4);
            cpa16(sA + adst[j], A + abase[j] + (bytes ? kg : 0), bytes);
        }
#pragma unroll
        for (int j = 0; j < 2; j++) {
            const __half2* src = W + ((long)(tt * 2 + nHalf) * 128 + bn[j]) * 16 + bc[j] * 4;
            cpa16(sB + bdst[j], src, 16);
        }
    };

    const int lm = ((lane >> 3) & 1) * 8 + (lane & 7);
    const int lc = lane >> 4;
    int apb[4], ahs4[4], ap7[4];
#pragma unroll
    for (int mi = 0; mi < 4; mi++) {
        int m = wm * 64 + mi * 16 + lm;
        apb[mi]  = (m >> 1) * 32;
        ahs4[mi] = (m & 1) * 4;
        ap7[mi]  = (m >> 1) & 7;
    }
    const int bl_m = lane >> 3;
    const int bl_r = lane & 7;
    const int b_half = bl_m & 1;
    int nb64[2], nbx[2];
#pragma unroll
    for (int ci = 0; ci < 2; ci++) {
        int ni = 2 * ci + (bl_m >> 1);
        int n  = wn * 32 + ni * 8 + bl_r;
        nb64[ci] = n * 64;
        nbx[ci]  = (n >> 1) & 3;
    }

    float acc[4][4][4];
#pragma unroll
    for (int mi = 0; mi < 4; mi++)
#pragma unroll
        for (int ni = 0; ni < 4; ni++)
#pragma unroll
            for (int c = 0; c < 4; c++) acc[mi][ni][c] = 0.f;

    const int nt = (Kp + 15) >> 4;
#pragma unroll
    for (int s = 0; s < 3; s++) {
        if (s < nt) issue(s, s);
        CP_COMMIT();
    }

    for (int tt = 0; tt < nt; tt++) {
        CP_WAIT2();
        __syncthreads();
        const int tn = tt + 3;
        if (tn < nt) issue(tn, tn & 3);
        CP_COMMIT();

        const uint32_t sA = sb + (uint32_t)(tt & 3) * 16384u;
        const uint32_t sB = sA + 8192u;
#pragma unroll
        for (int ks = 0; ks < 2; ks++) {
            unsigned a[4][4], b[4][2];
            const int c = 2 * ks + lc;
#pragma unroll
            for (int mi = 0; mi < 4; mi++) {
                uint32_t addr = sA + (uint32_t)((apb[mi] + ((ahs4[mi] + c) ^ ap7[mi]) * 4) * 4);
                LDSM_X4(a[mi][0], a[mi][1], a[mi][2], a[mi][3], addr);
            }
#pragma unroll
            for (int ci = 0; ci < 2; ci++) {
                uint32_t addr = sB + (uint32_t)(nb64[ci] + (((2 * ks + b_half) ^ nbx[ci]) << 4));
                LDSM_X4(b[2 * ci][0], b[2 * ci][1], b[2 * ci + 1][0], b[2 * ci + 1][1], addr);
            }
#pragma unroll
            for (int mi = 0; mi < 4; mi++)
#pragma unroll
                for (int ni = 0; ni < 4; ni++)
                    MMA_F16(acc[mi][ni], a[mi], b[ni]);
        }
    }

#pragma unroll
    for (int mi = 0; mi < 4; mi++) {
#pragma unroll
        for (int d = 0; d < 2; d++) {
            const long row = rowBase + wm * 64 + mi * 16 + g + d * 8;
#pragma unroll
            for (int ni = 0; ni < 4; ni++) {
                const int col = colBase + wn * 32 + ni * 8 + 2 * t;
                float v0 = acc[mi][ni][2 * d];
                float v1 = acc[mi][ni][2 * d + 1];
                if (EPI == 2) {
                    v0 += extra[row * 256 + col]; v1 += extra[row * 256 + col + 1];
                } else {
                    v0 += bias[col]; v1 += bias[col + 1];
                }
                v0 = fmaxf(v0, 0.f); v1 = fmaxf(v1, 0.f);
                if (OUTH)
                    Ch[row * 128 + (col >> 1)] = __floats2half2_rn(v0, v1);
                else
                    *reinterpret_cast<float2*>(&Cf[row * 256 + col]) = make_float2(v0, v1);
            }
        }
    }
}

// ---------------------------------------------------------------------------
// Dual-B FP16 GEMM: two GEMMs sharing A (same K), BM=64, BN=128, 256 thr,
// warp tile 32x32, 4-stage cp.async (stage = A 4KB + B1 8KB + B2 8KB).
// MODE 0: Cf1 = acc1 + bias1, Cf2 = acc2 + bias2 (fp32, linear)  [sev/spa]
// MODE 1: mu = acc1+bias1; lv = acc2+bias2;
//         z = fma(eps, exp(0.5*lv), mu) -> Chz half2              [mu/var/z]
// ---------------------------------------------------------------------------
#define DSTG_BYTES 20480
#define DSMEM_BYTES (4*DSTG_BYTES)   // 81920

template<int MODE>
__global__ void __launch_bounds__(256, 2)
hgemm_dual(const __half2* __restrict__ A, int lda,
           const __half2* __restrict__ W1,
           const __half2* __restrict__ W2,
           const float* __restrict__ bias1,
           const float* __restrict__ bias2,
           const float* __restrict__ eps,
           float* __restrict__ Cf1, float* __restrict__ Cf2,
           __half2* __restrict__ Chz,
           int Kp)
{
    extern __shared__ char sm[];
    const uint32_t sb = smem_u32(sm);
    const int tid  = threadIdx.x;
    const int lane = tid & 31;
    const int wid  = tid >> 5;
    const int wm   = wid >> 2;          // 0..1
    const int wn   = wid & 3;           // 0..3
    const int g    = lane >> 2;
    const int t    = lane & 3;

    const long rowBase = (long)blockIdx.y * 64;
    const int  nHalf   = blockIdx.x;
    const int  colBase = nHalf * 128;

    // A producer: 1 chunk of 16B per thread (64 rows x 4 chunks)
    const int am = tid >> 2;
    const int ac = tid & 3;
    const long abase = (rowBase + am) * (long)lda;
    const uint32_t adst = (uint32_t)(((am >> 1) * 32
                        + (((am & 1) * 4 + ac) ^ ((am >> 1) & 7)) * 4) * 4);
    // B producers: 2 chunks per thread per stream
    int bn[2], bc[2]; uint32_t bdst[2];
#pragma unroll
    for (int j = 0; j < 2; j++) {
        int idx = tid + j * 256;
        bn[j] = idx >> 2;
        bc[j] = idx & 3;
        bdst[j] = (uint32_t)(bn[j] * 64 + ((bc[j] ^ ((bn[j] >> 1) & 3)) << 4));
    }

    auto issue = [&](int tt, int s) {
        const int ktp = tt << 4;
        const uint32_t sA  = sb + (uint32_t)s * DSTG_BYTES;
        const uint32_t sB1 = sA + 4096u;
        const uint32_t sB2 = sA + 12288u;
        {
            int kg  = ktp + ac * 4;
            int rem = Kp - kg;
            int bytes = (rem <= 0) ? 0 : ((rem >= 4) ? 16 : rem * 4);
            cpa16(sA + adst, A + abase + (bytes ? kg : 0), bytes);
        }
#pragma unroll
        for (int j = 0; j < 2; j++) {
            const long woff = ((long)(tt * 2 + nHalf) * 128 + bn[j]) * 16 + bc[j] * 4;
            cpa16(sB1 + bdst[j], W1 + woff, 16);
            cpa16(sB2 + bdst[j], W2 + woff, 16);
        }
    };

    const int lm = ((lane >> 3) & 1) * 8 + (lane & 7);
    const int lc = lane >> 4;
    int apb[2], ahs4[2], ap7[2];
#pragma unroll
    for (int mi = 0; mi < 2; mi++) {
        int m = wm * 32 + mi * 16 + lm;
        apb[mi]  = (m >> 1) * 32;
        ahs4[mi] = (m & 1) * 4;
        ap7[mi]  = (m >> 1) & 7;
    }
    const int bl_m = lane >> 3;
    const int bl_r = lane & 7;
    const int b_half = bl_m & 1;
    int nb64[2], nbx[2];
#pragma unroll
    for (int ci = 0; ci < 2; ci++) {
        int ni = 2 * ci + (bl_m >> 1);
        int n  = wn * 32 + ni * 8 + bl_r;
        nb64[ci] = n * 64;
        nbx[ci]  = (n >> 1) & 3;
    }

    float acc1[2][4][4], acc2[2][4][4];
#pragma unroll
    for (int mi = 0; mi < 2; mi++)
#pragma unroll
        for (int ni = 0; ni < 4; ni++)
#pragma unroll
            for (int c = 0; c < 4; c++) { acc1[mi][ni][c] = 0.f; acc2[mi][ni][c] = 0.f; }

    const int nt = (Kp + 15) >> 4;
#pragma unroll
    for (int s = 0; s < 3; s++) {
        if (s < nt) issue(s, s);
        CP_COMMIT();
    }

    for (int tt = 0; tt < nt; tt++) {
        CP_WAIT2();
        __syncthreads();
        const int tn = tt + 3;
        if (tn < nt) issue(tn, tn & 3);
        CP_COMMIT();

        const uint32_t sA  = sb + (uint32_t)(tt & 3) * DSTG_BYTES;
        const uint32_t sB1 = sA + 4096u;
        const uint32_t sB2 = sA + 12288u;
#pragma unroll
        for (int ks = 0; ks < 2; ks++) {
            unsigned a[2][4], b1[4][2], b2[4][2];
            const int c = 2 * ks + lc;
#pragma unroll
            for (int mi = 0; mi < 2; mi++) {
                uint32_t addr = sA + (uint32_t)((apb[mi] + ((ahs4[mi] + c) ^ ap7[mi]) * 4) * 4);
                LDSM_X4(a[mi][0], a[mi][1], a[mi][2], a[mi][3], addr);
            }
#pragma unroll
            for (int ci = 0; ci < 2; ci++) {
                const uint32_t off = (uint32_t)(nb64[ci] + (((2 * ks + b_half) ^ nbx[ci]) << 4));
                LDSM_X4(b1[2 * ci][0], b1[2 * ci][1], b1[2 * ci + 1][0], b1[2 * ci + 1][1], sB1 + off);
                LDSM_X4(b2[2 * ci][0], b2[2 * ci][1], b2[2 * ci + 1][0], b2[2 * ci + 1][1], sB2 + off);
            }
#pragma unroll
            for (int mi = 0; mi < 2; mi++)
#pragma unroll
                for (int ni = 0; ni < 4; ni++) {
                    MMA_F16(acc1[mi][ni], a[mi], b1[ni]);
                    MMA_F16(acc2[mi][ni], a[mi], b2[ni]);
                }
        }
    }

#pragma unroll
    for (int mi = 0; mi < 2; mi++) {
#pragma unroll
        for (int d = 0; d < 2; d++) {
            const long row = rowBase + wm * 32 + mi * 16 + g + d * 8;
#pragma unroll
            for (int ni = 0; ni < 4; ni++) {
                const int col = colBase + wn * 32 + ni * 8 + 2 * t;
                float u0 = acc1[mi][ni][2 * d]     + bias1[col];
                float u1 = acc1[mi][ni][2 * d + 1] + bias1[col + 1];
                float w0 = acc2[mi][ni][2 * d]     + bias2[col];
                float w1 = acc2[mi][ni][2 * d + 1] + bias2[col + 1];
                if (MODE == 0) {
                    *reinterpret_cast<float2*>(&Cf1[row * 256 + col]) = make_float2(u0, u1);
                    *reinterpret_cast<float2*>(&Cf2[row * 256 + col]) = make_float2(w0, w1);
                } else {
                    float z0 = fmaf(eps[row * 256 + col],     expf(0.5f * w0), u0);
                    float z1 = fmaf(eps[row * 256 + col + 1], expf(0.5f * w1), u1);
                    Chz[row * 128 + (col >> 1)] = __floats2half2_rn(z0, z1);
                }
            }
        }
    }
}

// ---------------------------------------------------------------------------
// Fused oth -> (k, v), fp16 + ldmatrix A&B. Per CTA: 128 agent rows, 512 thr.
// smem words: OTH 16384 (interleaved, prow=256), A1 2048 (prow=32),
//             4 B stages x 2048 (n-major blocked layout).
// ---------------------------------------------------------------------------
#define F_OTH 0
#define F_A1  16384
#define F_STG 18432
#define FSMEM_BYTES 106496

__global__ void __launch_bounds__(512, 2)
fused_okv(const __half2* __restrict__ xh,
          const __half2* __restrict__ WBoth, const float* __restrict__ both,
          const __half2* __restrict__ WBk,   const float* __restrict__ bk_,
          const __half2* __restrict__ WBvlo,
          const float* __restrict__ sev,
          __half2* __restrict__ kb, __half2* __restrict__ vb)
{
    extern __shared__ char sm[];
    unsigned* smw = (unsigned*)sm;
    const uint32_t sb = smem_u32(sm);
    const int tid  = threadIdx.x;
    const int lane = tid & 31;
    const int wid  = tid >> 5;
    const int wm   = wid >> 2;   // 0..3
    const int wn   = wid & 3;    // 0..3
    const int g    = lane >> 2;
    const int t    = lane & 3;
    const long rowBase = (long)blockIdx.x * 128;

    const int lm = ((lane >> 3) & 1) * 8 + (lane & 7);
    const int lc = lane >> 4;
    int apbO[2], apbA[2], ahs4[2], ap7[2];
#pragma unroll
    for (int mi = 0; mi < 2; mi++) {
        int m = wm * 32 + mi * 16 + lm;
        apbO[mi] = (m >> 1) * 256;
        apbA[mi] = (m >> 1) * 32;
        ahs4[mi] = (m & 1) * 4;
        ap7[mi]  = (m >> 1) & 7;
    }
    const int bl_m = lane >> 3;
    const int bl_r = lane & 7;
    const int b_half = bl_m & 1;
    int nb64[2], nbx[2];
#pragma unroll
    for (int ci = 0; ci < 2; ci++) {
        int ni = 2 * ci + (bl_m >> 1);
        int n  = wn * 32 + ni * 8 + bl_r;
        nb64[ci] = n * 64;
        nbx[ci]  = (n >> 1) & 3;
    }
    const int pn = tid >> 2, pc = tid & 3;
    const uint32_t pdst = (uint32_t)(pn * 64 + ((pc ^ ((pn >> 1) & 3)) << 4));

    for (int it = tid; it < 2048; it += 512) {
        const int m = it >> 4, w = it & 15;
        unsigned val = 0;
        if (w < 14) {
            long row = rowBase + m;
            int bb = (int)(row / NOTH);
            int nn = (int)(row - (long)bb * NOTH);
            val = *reinterpret_cast<const unsigned*>(&xh[(long)bb * XWP + 18 + nn * 14 + w]);
        }
        const int p = m >> 1, hs = m & 1, c = w >> 2, win = w & 3;
        smw[F_A1 + p * 32 + ((hs * 4 + c) ^ (p & 7)) * 4 + win] = val;
    }
#pragma unroll
    for (int h = 0; h < 2; h++) {
        const __half2* src = WBoth + ((long)h * 128 + pn) * 16 + pc * 4;
        cpa16(sb + (uint32_t)(F_STG + h * 2048) * 4 + pdst, src, 16);
    }
    CP_COMMIT();
    asm volatile("cp.async.wait_group 0;" ::: "memory");
    __syncthreads();

    for (int h = 0; h < 2; h++) {
        float acc[2][4][4];
#pragma unroll
        for (int mi = 0; mi < 2; mi++)
#pragma unroll
            for (int ni = 0; ni < 4; ni++)
#pragma unroll
                for (int c = 0; c < 4; c++) acc[mi][ni][c] = 0.f;
        const uint32_t sB = sb + (uint32_t)(F_STG + h * 2048) * 4;
#pragma unroll
        for (int ks = 0; ks < 2; ks++) {
            unsigned a[2][4], b[4][2];
            const int c = 2 * ks + lc;
#pragma unroll
            for (int mi = 0; mi < 2; mi++) {
                uint32_t addr = sb + (uint32_t)((F_A1 + apbA[mi] + ((ahs4[mi] + c) ^ ap7[mi]) * 4) * 4);
                LDSM_X4(a[mi][0], a[mi][1], a[mi][2], a[mi][3], addr);
            }
#pragma unroll
            for (int ci = 0; ci < 2; ci++) {
                uint32_t addr = sB + (uint32_t)(nb64[ci] + (((2 * ks + b_half) ^ nbx[ci]) << 4));
                LDSM_X4(b[2 * ci][0], b[2 * ci][1], b[2 * ci + 1][0], b[2 * ci + 1][1], addr);
            }
#pragma unroll
            for (int mi = 0; mi < 2; mi++)
#pragma unroll
                for (int ni = 0; ni < 4; ni++)
                    MMA_F16(acc[mi][ni], a[mi], b[ni]);
        }
#pragma unroll
        for (int mi = 0; mi < 2; mi++)
#pragma unroll
            for (int d = 0; d < 2; d++) {
                const int rm = wm * 32 + mi * 16 + g + d * 8;
                const int p = rm >> 1, hs = rm & 1;
#pragma unroll
                for (int ni = 0; ni < 4; ni++) {
                    const int col = h * 128 + wn * 32 + ni * 8 + 2 * t;
                    float v0 = fmaxf(acc[mi][ni][2 * d]     + both[col],     0.f);
                    float v1 = fmaxf(acc[mi][ni][2 * d + 1] + both[col + 1], 0.f);
                    __half2 hv = __floats2half2_rn(v0, v1);
                    const int line = h * 4 + wn;
                    smw[F_OTH + p * 256 + line * 32 + ((hs * 4 + ni) ^ (p & 7)) * 4 + t] =
                        *reinterpret_cast<unsigned*>(&hv);
                }
            }
    }
    __syncthreads();

    for (int cc = 0; cc < 4; cc++) {
        const __half2* W = (cc < 2) ? WBk : WBvlo;
        const int nh = cc & 1;
        __half2* Co = (cc < 2) ? kb : vb;
        const int colOff = nh * 128;

        auto issueB = [&](int tt, int s) {
            const __half2* src = W + ((long)(tt * 2 + nh) * 128 + pn) * 16 + pc * 4;
            cpa16(sb + (uint32_t)(F_STG + s * 2048) * 4 + pdst, src, 16);
        };

        float acc[2][4][4];
#pragma unroll
        for (int mi = 0; mi < 2; mi++)
#pragma unroll
            for (int ni = 0; ni < 4; ni++)
#pragma unroll
                for (int c = 0; c < 4; c++) acc[mi][ni][c] = 0.f;

#pragma unroll
        for (int s = 0; s < 3; s++) {
            issueB(s, s);
            CP_COMMIT();
        }

        for (int tt = 0; tt < 8; tt++) {
            CP_WAIT2();
            __syncthreads();
            if (tt + 3 < 8) issueB(tt + 3, (tt + 3) & 3);
            CP_COMMIT();

            const uint32_t sB = sb + (uint32_t)(F_STG + (tt & 3) * 2048) * 4;
#pragma unroll
            for (int ks = 0; ks < 2; ks++) {
                unsigned a[2][4], b[4][2];
                const int c3 = 2 * ks + lc;
#pragma unroll
                for (int mi = 0; mi < 2; mi++) {
                    uint32_t addr = sb + (uint32_t)((F_OTH + apbO[mi] + tt * 32
                                     + ((ahs4[mi] + c3) ^ ap7[mi]) * 4) * 4);
                    LDSM_X4(a[mi][0], a[mi][1], a[mi][2], a[mi][3], addr);
                }
#pragma unroll
                for (int ci = 0; ci < 2; ci++) {
                    uint32_t addr = sB + (uint32_t)(nb64[ci] + (((2 * ks + b_half) ^ nbx[ci]) << 4));
                    LDSM_X4(b[2 * ci][0], b[2 * ci][1], b[2 * ci + 1][0], b[2 * ci + 1][1], addr);
                }
#pragma unroll
                for (int mi = 0; mi < 2; mi++)
#pragma unroll
                    for (int ni = 0; ni < 4; ni++)
                        MMA_F16(acc[mi][ni], a[mi], b[ni]);
            }
        }

#pragma unroll
        for (int mi = 0; mi < 2; mi++)
#pragma unroll
            for (int d = 0; d < 2; d++) {
                const long row = rowBase + wm * 32 + mi * 16 + g + d * 8;
                const float* sv = (cc >= 2) ? (sev + (row / NOTH) * 256) : nullptr;
#pragma unroll
                for (int ni = 0; ni < 4; ni++) {
                    const int col = colOff + wn * 32 + ni * 8 + 2 * t;
                    float v0 = acc[mi][ni][2 * d];
                    float v1 = acc[mi][ni][2 * d + 1];
                    if (cc < 2) { v0 += bk_[col]; v1 += bk_[col + 1]; }
                    else        { v0 += sv[col];  v1 += sv[col + 1]; }
                    v0 = fmaxf(v0, 0.f); v1 = fmaxf(v1, 0.f);
                    Co[row * 128 + (col >> 1)] = __floats2half2_rn(v0, v1);
                }
            }
    }
}

// ---------------------------------------------------------------------------
// Packing kernels
// ---------------------------------------------------------------------------
__global__ void packWB(const float* __restrict__ Wmu, const float* __restrict__ Wvar,
                       const float* __restrict__ Wself, const float* __restrict__ Woth,
                       const float* __restrict__ Wq, const float* __restrict__ Wk,
                       const float* __restrict__ Wv, const float* __restrict__ Wa,
                       __half2* __restrict__ out)
{
    int i = blockIdx.x * blockDim.x + threadIdx.x;
    if (i >= WB_END) return;
    const float* src; int base, kpOff, kpLen;
    if      (i < WB_VAR)  { src = Wmu;   base = WB_MU;   kpOff = 0;   kpLen = 284; }
    else if (i < WB_SELF) { src = Wvar;  base = WB_VAR;  kpOff = 0;   kpLen = 284; }
    else if (i < WB_OTH)  { src = Wself; base = WB_SELF; kpOff = 0;   kpLen = 18;  }
    else if (i < WB_Q)    { src = Woth;  base = WB_OTH;  kpOff = 0;   kpLen = 14;  }
    else if (i < WB_K)    { src = Wq;    base = WB_Q;    kpOff = 0;   kpLen = 128; }
    else if (i < WB_VLO)  { src = Wk;    base = WB_K;    kpOff = 0;   kpLen = 128; }
    else if (i < WB_VHI)  { src = Wv;    base = WB_VLO;  kpOff = 0;   kpLen = 128; }
    else if (i < WB_ALO)  { src = Wv;    base = WB_VHI;  kpOff = 128; kpLen = 128; }
    else if (i < WB_AHI)  { src = Wa;    base = WB_ALO;  kpOff = 0;   kpLen = 128; }
    else                  { src = Wa;    base = WB_AHI;  kpOff = 128; kpLen = 128; }
    int r    = i - base;
    int tile = r >> 12;
    int rem  = r & 4095;
    int half = rem >> 11;
    int n    = (rem >> 4) & 127;
    int kp   = rem & 15;
    int kpl  = tile * 16 + kp;
    __half2 v = __floats2half2_rn(0.f, 0.f);
    if (kpl < kpLen) {
        int k   = kpOff + kpl;
        int col = half * 128 + n;
        v = __floats2half2_rn(src[(2 * k) * 256 + col], src[(2 * k + 1) * 256 + col]);
    }
    out[i] = v;
}
__global__ void packX(const float2* __restrict__ in, __half2* __restrict__ out, int n)
{
    int i = blockIdx.x * blockDim.x + threadIdx.x;
    if (i < n) {
        float2 f = in[i];
        out[i] = __floats2half2_rn(f.x, f.y);
    }
}

// ---------------------------------------------------------------------------
// Attention: scores = q.k/16 -> softmax(19) -> h = att @ v (half2 I/O)
// ---------------------------------------------------------------------------
__global__ void __launch_bounds__(256)
att_kernel(const float* __restrict__ q,
           const __half2* __restrict__ k2,
           const __half2* __restrict__ v2,
           __half2* __restrict__ h2,
           float* __restrict__ att_out)
{
    const int b   = blockIdx.x;
    const int tid = threadIdx.x;
    const int wid = tid >> 5;
    const int lane = tid & 31;

    __shared__ float qs[HDIM];
    __shared__ float sc[32];

    qs[tid] = q[(long)b * HDIM + tid];
    __syncthreads();

    for (int n = wid; n < NOTH; n += 8) {
        const __half2* kp = k2 + ((long)b * NOTH + n) * 128;
        float p = 0.f;
#pragma unroll
        for (int j = 0; j < 4; j++) {
            const int w = lane + 32 * j;
            float2 f = __half22float2(kp[w]);
            p = fmaf(qs[2 * w], f.x, p);
            p = fmaf(qs[2 * w + 1], f.y, p);
        }
#pragma unroll
        for (int off = 16; off > 0; off >>= 1)
            p += __shfl_xor_sync(0xffffffffu, p, off);
        if (lane == 0) sc[n] = p * 0.0625f;
    }
    __syncthreads();

    if (wid == 0) {
        float s = (lane < NOTH) ? sc[lane] : -INFINITY;
        float m = s;
#pragma unroll
        for (int off = 16; off > 0; off >>= 1)
            m = fmaxf(m, __shfl_xor_sync(0xffffffffu, m, off));
        float e = (lane < NOTH) ? expf(s - m) : 0.f;
        float sum = e;
#pragma unroll
        for (int off = 16; off > 0; off >>= 1)
            sum += __shfl_xor_sync(0xffffffffu, sum, off);
        const float a = e / sum;
        if (lane < NOTH) {
            sc[lane] = a;
            att_out[(long)b * NOTH + lane] = a;
        }
    }
    __syncthreads();

    if (tid < 128) {
        const __half2* vp = v2 + (long)b * NOTH * 128 + tid;
        float ax = 0.f, ay = 0.f;
#pragma unroll
        for (int n = 0; n < NOTH; n++) {
            float2 f = __half22float2(vp[(long)n * 128]);
            ax = fmaf(sc[n], f.x, ax);
            ay = fmaf(sc[n], f.y, ay);
        }
        h2[(long)b * 128 + tid] = __floats2half2_rn(ax, ay);
    }
}

// ---------------------------------------------------------------------------
// Launch
// ---------------------------------------------------------------------------
extern "C" void kernel_launch(void* const* d_in, const int* in_sizes, int n_in,
                              void* d_out, int out_size)
{
    const float* x      = (const float*)d_in[0];
    const float* eps    = (const float*)d_in[1];
    const float* W_mu   = (const float*)d_in[2];
    const float* b_mu   = (const float*)d_in[3];
    const float* W_var  = (const float*)d_in[4];
    const float* b_var  = (const float*)d_in[5];
    const float* W_self = (const float*)d_in[6];
    const float* b_self = (const float*)d_in[7];
    const float* W_oth  = (const float*)d_in[8];
    const float* b_oth  = (const float*)d_in[9];
    const float* W_q    = (const float*)d_in[10];
    const float* b_q    = (const float*)d_in[11];
    const float* W_k    = (const float*)d_in[12];
    const float* b_k    = (const float*)d_in[13];
    const float* W_v    = (const float*)d_in[14];
    const float* b_v    = (const float*)d_in[15];
    const float* W_a    = (const float*)d_in[16];
    const float* b_a    = (const float*)d_in[17];

    float* out_main = (float*)d_out;
    float* out_att  = (float*)d_out + (long)BATCH * HDIM;

    float *q, *sev, *spa;
    __half2 *zh, *selfh, *hh, *kh, *vh, *xh, *wp;
    cudaGetSymbolAddress((void**)&q,     g_q);
    cudaGetSymbolAddress((void**)&sev,   g_sev);
    cudaGetSymbolAddress((void**)&spa,   g_spa);
    cudaGetSymbolAddress((void**)&zh,    g_zh);
    cudaGetSymbolAddress((void**)&selfh, g_selfh);
    cudaGetSymbolAddress((void**)&hh,    g_hh);
    cudaGetSymbolAddress((void**)&kh,    g_kh);
    cudaGetSymbolAddress((void**)&vh,    g_vh);
    cudaGetSymbolAddress((void**)&xh,    g_xh);
    cudaGetSymbolAddress((void**)&wp,    g_wp);

    cudaFuncSetAttribute(hgemm<1,0>,    cudaFuncAttributeMaxDynamicSharedMemorySize, GS1_BYTES);
    cudaFuncSetAttribute(hgemm<1,1>,    cudaFuncAttributeMaxDynamicSharedMemorySize, GS1_BYTES);
    cudaFuncSetAttribute(hgemm<2,0>,    cudaFuncAttributeMaxDynamicSharedMemorySize, GS1_BYTES);
    cudaFuncSetAttribute(hgemm_dual<0>, cudaFuncAttributeMaxDynamicSharedMemorySize, DSMEM_BYTES);
    cudaFuncSetAttribute(hgemm_dual<1>, cudaFuncAttributeMaxDynamicSharedMemorySize, DSMEM_BYTES);
    cudaFuncSetAttribute(fused_okv,     cudaFuncAttributeMaxDynamicSharedMemorySize, FSMEM_BYTES);

    // Pack operands (blocked weights + half2 x)
    packWB<<<(WB_END + 255) / 256, 256>>>(W_mu, W_var, W_self, W_oth,
                                          W_q, W_k, W_v, W_a, wp);
    {
        int nx = BATCH * XWP;
        packX<<<(nx + 255) / 256, 256>>>((const float2*)x, xh, nx);
    }

    const dim3 blk(256);
    const dim3 gB1(2, BATCH / 128);  // single-B GEMMs (BM=128)
    const dim3 gD (2, BATCH / 64);   // dual-B GEMMs (BM=64)

    // z = eps * exp(0.5*(x@W_var+b_var)) + (x@W_mu+b_mu)   [one dual GEMM]
    hgemm_dual<1><<<gD, blk, DSMEM_BYTES>>>(xh, XWP, wp + WB_MU, wp + WB_VAR,
                                            b_mu, b_var, eps, nullptr, nullptr, zh, 284);
    // self_em = relu(x[:, :36] @ W_self + b) (half out)
    hgemm<1,1><<<gB1, blk, GS1_BYTES>>>(xh, XWP, wp + WB_SELF, b_self, nullptr, nullptr, selfh, 18);
    // sev = self_em @ W_v[256:] + b_v ; spa = self_em @ W_a[256:] + b_a  [one dual GEMM]
    hgemm_dual<0><<<gD, blk, DSMEM_BYTES>>>(selfh, 128, wp + WB_VHI, wp + WB_AHI,
                                            b_v, b_a, nullptr, sev, spa, nullptr, 128);
    // fused: oth (smem) -> k, v (half out)
    fused_okv<<<MROWS / 128, 512, FSMEM_BYTES>>>(xh, wp + WB_OTH, b_oth,
                                                 wp + WB_K, b_k, wp + WB_VLO,
                                                 sev, kh, vh);
    // q = relu(z @ W_q + b) (fp32 out; feeds att only)
    hgemm<1,0><<<gB1, blk, GS1_BYTES>>>(zh, 128, wp + WB_Q, b_q, nullptr, q, nullptr, 128);
    // attention
    att_kernel<<<BATCH, 256>>>(q, kh, vh, hh, out_att);
    // out = relu(h @ W_a[:256] + spa) (fp32 out)
    hgemm<2,0><<<gB1, blk, GS1_BYTES>>>(hh, 128, wp + WB_ALO, nullptr, spa, out_main, nullptr, 128);
}